// round 12
// baseline (speedup 1.0000x reference)
#include <cuda_runtime.h>
#include <cstdint>

// Warp-autonomous, 4 rows/thread. Each warp owns 128 contiguous rows
// (288 float4 = 9 exact cp.async rounds in, 96 float4 = 3 exact rounds out).
// No block barriers, no partial rounds. All smem ops 128-bit, conflict-free.
// 18 KB smem / 128-thread block, 12 CTAs/SM target.

constexpr int TPB = 128;                  // 4 warps
constexpr int RPW = 128;                  // rows per warp
constexpr int RPB = 512;                  // rows per block
constexpr int IN4_W = RPW * 9 / 4;        // 288 float4 per warp (4608 B)
constexpr int IN4_B = 4 * IN4_W;          // 1152 float4 = 18432 B
constexpr int OUT4_W = RPW * 3 / 4;       // 96 float4 per warp

__device__ __forceinline__ void process_row(const float* __restrict__ x,
                                            float* __restrict__ o)
{
    int mi[3];
#pragma unroll
    for (int j = 0; j < 3; j++) {
        float a0 = x[3*j], a1 = x[3*j+1], a2 = x[3*j+2];
        bool q0 = (a0 > a1) && (a0 > a2);
        bool q2 = (a2 > a0) && (a2 > a1);
        mi[j] = (int)q0 - (int)q2;
    }
    int calc = ((mi[1] < 0) ? -mi[1] : mi[1]) * (mi[0] + mi[1] + mi[2]);
    int sc   = (calc > 0) - (calc < 0);

    float m[9];
#pragma unroll
    for (int j = 0; j < 3; j++) {
        bool keep = (mi[j] == sc);
#pragma unroll
        for (int k = 0; k < 3; k++)
            m[3*j + k] = keep ? x[3*j + k] : 0.0f;
    }
    float v0, v1, v2;
    if (sc == 0)      { v0 = m[1]; v1 = m[4]; v2 = m[7]; }
    else if (sc > 0)  { v0 = m[0]; v1 = m[3]; v2 = m[6]; }
    else              { v0 = m[2]; v1 = m[5]; v2 = m[8]; }

    bool b1 = (v1 > v0);
    float best01 = b1 ? v1 : v0;
    bool b2 = (v2 > best01);
#pragma unroll
    for (int k = 0; k < 3; k++) {
        float t01 = b1 ? m[3 + k] : m[k];
        o[k] = b2 ? m[6 + k] : t01;
    }
}

__global__ void __launch_bounds__(TPB, 12) concat_w4(
    const float4* __restrict__ in4, float4* __restrict__ out4)
{
    __shared__ float4 s[IN4_B];           // 18432 B, per-warp regions, reused

    const int lane = threadIdx.x & 31;
    const int w    = threadIdx.x >> 5;

    float4* sw = s + w * IN4_W;           // this warp's 4608 B region
    const size_t ibase = (size_t)blockIdx.x * IN4_B + w * IN4_W;

    // Warp-local staging: exactly 9 full rounds of cp.async.cg
#pragma unroll
    for (int i = 0; i < 9; i++) {
        uint32_t dst = (uint32_t)__cvta_generic_to_shared(&sw[i * 32 + lane]);
        const float4* src = in4 + ibase + i * 32 + lane;
        asm volatile("cp.async.cg.shared.global [%0], [%1], 16;"
                     :: "r"(dst), "l"(src) : "memory");
    }
    asm volatile("cp.async.commit_group;" ::: "memory");
    asm volatile("cp.async.wait_group 0;" ::: "memory");
    __syncwarp();

    // 4 rows = 9 LDS.128 @ 144B lane stride (conflict-free: 8-lane phases
    // start at banks {0,4,...,28}, each covering 4 banks -> all 32 once)
    float x[36];
#pragma unroll
    for (int k = 0; k < 9; k++) {
        float4 v = sw[lane * 9 + k];
        x[4*k+0] = v.x; x[4*k+1] = v.y; x[4*k+2] = v.z; x[4*k+3] = v.w;
    }
    __syncwarp();                         // warp's reads done before reuse

    float o[12];
#pragma unroll
    for (int r = 0; r < 4; r++)
        process_row(x + 9*r, o + 3*r);

    // Restage output in-place: 3 STS.128 @ 48B stride (conflict-free:
    // start banks {0,12,24,4,16,28,8,20} x4 consecutive -> all 32 once)
#pragma unroll
    for (int k = 0; k < 3; k++) {
        float4 v;
        v.x = o[4*k+0]; v.y = o[4*k+1]; v.z = o[4*k+2]; v.w = o[4*k+3];
        sw[lane * 3 + k] = v;
    }
    __syncwarp();

    // Warp-local coalesced store: exactly 3 full rounds
    const size_t obase = (size_t)blockIdx.x * (4 * OUT4_W) + w * OUT4_W;
#pragma unroll
    for (int i = 0; i < 3; i++)
        __stcs(&out4[obase + i * 32 + lane], sw[i * 32 + lane]);
}

// Scalar tail for n_rows % 512 != 0 (not hit for N = 2^23)
__global__ void concat_tail(const float* __restrict__ in,
                            float* __restrict__ out,
                            int row_start, int n_rows)
{
    int row = row_start + blockIdx.x * blockDim.x + threadIdx.x;
    if (row >= n_rows) return;
    float x[9];
#pragma unroll
    for (int k = 0; k < 9; k++) x[k] = in[(size_t)row * 9 + k];
    float o[3];
    process_row(x, o);
#pragma unroll
    for (int k = 0; k < 3; k++) out[(size_t)row * 3 + k] = o[k];
}

extern "C" void kernel_launch(void* const* d_in, const int* in_sizes, int n_in,
                              void* d_out, int out_size)
{
    const float* in = (const float*)d_in[0];
    float* out = (float*)d_out;
    int n_rows = in_sizes[0] / 9;

    int nfull = n_rows / RPB;
    if (nfull > 0)
        concat_w4<<<nfull, TPB>>>((const float4*)in, (float4*)out);

    int done = nfull * RPB;
    int rem = n_rows - done;
    if (rem > 0) {
        int grid = (rem + 255) / 256;
        concat_tail<<<grid, 256>>>(in, out, done, n_rows);
    }
}